// round 1
// baseline (speedup 1.0000x reference)
#include <cuda_runtime.h>
#include <math.h>

// Problem constants (fixed by the dataset)
#define NBLK 512      // NB = B * BLOCKS_PER_SEQ
#define BQ   32       // B
#define HH   16       // H
#define DD   576      // KV_LORA + ROPE
#define DVV  512      // KV_LORA
#define BSS  128      // BS (tokens per block)
#define QSCALE 0.07216878364870322f  // 192^-0.5

// Scratch (device globals — no allocation allowed)
__device__ float g_oacc[NBLK * HH * DVV];   // 16 MB partial outputs
__device__ float g_bm[NBLK * HH];           // per-block max
__device__ float g_bs[NBLK * HH];           // per-block sum

// -----------------------------------------------------------------------------
// Kernel 1: one CTA per KV block n. Computes attn = q·kv + bias, per-block
// softmax (max/sum), and o_partial = p·v into g_oacc.
//
// SMEM layout (floats):
//   qs   [16][576]        9216   (scaled q for this block's group)
//   kvs  [8192]           8192   (K chunk 128x64 in pass A / V tile 16x512 in pass C)
//   attn [16][132]        2112   (132 stride to break bank conflicts)
// -----------------------------------------------------------------------------
#define ATT_STRIDE 132
#define SMEM_FLOATS (9216 + 8192 + HH * ATT_STRIDE)

__global__ __launch_bounds__(256, 2) void mla_block_kernel(
    const float* __restrict__ query,
    const float* __restrict__ key_cache,
    const float* __restrict__ block_bias,
    const int* __restrict__ block_list,
    const int* __restrict__ block_groups)
{
    extern __shared__ float sm[];
    float* qs   = sm;                  // 9216
    float* kvs  = sm + 9216;           // 8192
    float* attn = sm + 9216 + 8192;    // 16 * 132

    const int t = threadIdx.x;
    const int n = blockIdx.x;
    const int b = block_groups[n];
    const long blk = (long)block_list[n];
    const float* kvb = key_cache + blk * (long)(BSS * DD);

    // ---- load q for this group, pre-scaled (2304 float4 / 256 thr = 9 each)
    {
        const float4* qg = (const float4*)(query + (long)b * HH * DD);
        float4* qs4 = (float4*)qs;
        #pragma unroll
        for (int i = 0; i < 9; i++) {
            float4 v = qg[t + i * 256];
            v.x *= QSCALE; v.y *= QSCALE; v.z *= QSCALE; v.w *= QSCALE;
            qs4[t + i * 256] = v;
        }
    }

    // ---- Pass A: attn accumulation, streaming K in chunks of 64 d-columns.
    // Thread micro-tile: 2 heads x 4 s-rows.
    float acc[2][4];
    #pragma unroll
    for (int i = 0; i < 2; i++)
        #pragma unroll
        for (int j = 0; j < 4; j++) acc[i][j] = 0.f;

    const int hblk = t & 7;    // 8 head-pairs
    const int sblk = t >> 3;   // 32 s-quads
    const int lcol = t & 15;   // loader: float4 column
    const int lrow = t >> 4;   // loader: base row

    float4* kvs4 = (float4*)kvs;
    const float4* qs4 = (const float4*)qs;

    for (int kc = 0; kc < 9; kc++) {
        __syncthreads();
        // load K chunk: rows 0..127, float4 cols [kc*16, kc*16+16)
        #pragma unroll
        for (int r = 0; r < 8; r++) {
            int s = lrow + r * 16;
            kvs4[s * 16 + lcol] =
                *(const float4*)(kvb + (long)s * DD + kc * 64 + lcol * 4);
        }
        __syncthreads();
        #pragma unroll
        for (int k4 = 0; k4 < 16; k4++) {
            float4 q0 = qs4[(hblk * 2 + 0) * 144 + kc * 16 + k4];
            float4 q1 = qs4[(hblk * 2 + 1) * 144 + kc * 16 + k4];
            #pragma unroll
            for (int j = 0; j < 4; j++) {
                float4 kv = kvs4[(sblk * 4 + j) * 16 + k4];
                acc[0][j] += q0.x * kv.x + q0.y * kv.y + q0.z * kv.z + q0.w * kv.w;
                acc[1][j] += q1.x * kv.x + q1.y * kv.y + q1.z * kv.z + q1.w * kv.w;
            }
        }
    }
    __syncthreads();
    // write attn (+bias) to smem
    #pragma unroll
    for (int i = 0; i < 2; i++)
        #pragma unroll
        for (int j = 0; j < 4; j++) {
            int h = hblk * 2 + i, s = sblk * 4 + j;
            attn[h * ATT_STRIDE + s] = acc[i][j] + block_bias[n * BSS + s];
        }
    __syncthreads();

    // ---- Pass B: per-(n,h) softmax. 16 threads per head.
    {
        int h = t >> 4, ln = t & 15;
        float m = -1e30f;
        #pragma unroll
        for (int r = 0; r < 8; r++)
            m = fmaxf(m, attn[h * ATT_STRIDE + ln + r * 16]);
        #pragma unroll
        for (int o = 8; o >= 1; o >>= 1)
            m = fmaxf(m, __shfl_xor_sync(0xffffffffu, m, o, 16));
        float l = 0.f;
        #pragma unroll
        for (int r = 0; r < 8; r++) {
            int idx = h * ATT_STRIDE + ln + r * 16;
            float p = __expf(attn[idx] - m);
            attn[idx] = p;
            l += p;
        }
        #pragma unroll
        for (int o = 8; o >= 1; o >>= 1)
            l += __shfl_xor_sync(0xffffffffu, l, o, 16);
        if (ln == 0) {
            g_bm[n * HH + h] = m;
            g_bs[n * HH + h] = l;
        }
    }

    // ---- Pass C: o = p @ v, streaming V in tiles of 16 s-rows x 512 v.
    // Thread micro-tile: 2 heads x 16 v.
    float4 o4[2][4];
    #pragma unroll
    for (int i = 0; i < 2; i++)
        #pragma unroll
        for (int j = 0; j < 4; j++) o4[i][j] = make_float4(0.f, 0.f, 0.f, 0.f);

    const int hb = t & 7;     // 8 head-pairs
    const int vb = t >> 3;    // 32 v-chunks of 16

    for (int st = 0; st < 8; st++) {
        __syncthreads();
        // load V tile: rows st*16..+16, first 512 cols (128 float4 per row)
        #pragma unroll
        for (int c = 0; c < 8; c++) {
            kvs4[lrow * 128 + lcol + c * 16] =
                *(const float4*)(kvb + (long)(st * 16 + lrow) * DD + (lcol + c * 16) * 4);
        }
        __syncthreads();
        #pragma unroll
        for (int s = 0; s < 16; s++) {
            float p0 = attn[(hb * 2 + 0) * ATT_STRIDE + st * 16 + s];
            float p1 = attn[(hb * 2 + 1) * ATT_STRIDE + st * 16 + s];
            #pragma unroll
            for (int jj = 0; jj < 4; jj++) {
                float4 vv = kvs4[s * 128 + vb * 4 + jj];
                o4[0][jj].x += p0 * vv.x; o4[0][jj].y += p0 * vv.y;
                o4[0][jj].z += p0 * vv.z; o4[0][jj].w += p0 * vv.w;
                o4[1][jj].x += p1 * vv.x; o4[1][jj].y += p1 * vv.y;
                o4[1][jj].z += p1 * vv.z; o4[1][jj].w += p1 * vv.w;
            }
        }
    }

    // ---- store partial o
    #pragma unroll
    for (int i = 0; i < 2; i++) {
        int h = hb * 2 + i;
        float4* dst = (float4*)(g_oacc + ((long)(n * HH + h)) * DVV + vb * 16);
        #pragma unroll
        for (int jj = 0; jj < 4; jj++) dst[jj] = o4[i][jj];
    }
}

// -----------------------------------------------------------------------------
// Kernel 2: combine across the blocks of each group (split-KV softmax merge).
// Grid (B, H), 128 threads; thread t owns float4 at v = 4*t.
// -----------------------------------------------------------------------------
__global__ __launch_bounds__(128) void mla_combine_kernel(
    const int* __restrict__ block_groups,
    float* __restrict__ out)
{
    const int b = blockIdx.x, h = blockIdx.y, t = threadIdx.x;
    __shared__ int mem[NBLK];
    __shared__ int cnt;

    // deterministic ordered member gather via warp ballot (warp 0 only)
    if (t < 32) {
        int c = 0;
        for (int base = 0; base < NBLK; base += 32) {
            int i = base + t;
            bool hit = (block_groups[i] == b);
            unsigned bal = __ballot_sync(0xffffffffu, hit);
            if (hit) mem[c + __popc(bal & ((1u << t) - 1u))] = i;
            c += __popc(bal);
        }
        if (t == 0) cnt = c;
    }
    __syncthreads();
    const int C = cnt;

    float gmax = -1e30f;
    for (int j = 0; j < C; j++)
        gmax = fmaxf(gmax, g_bm[mem[j] * HH + h]);
    float gsum = 0.f;
    for (int j = 0; j < C; j++)
        gsum += g_bs[mem[j] * HH + h] * __expf(g_bm[mem[j] * HH + h] - gmax);
    const float inv = 1.f / gsum;

    float4 acc = make_float4(0.f, 0.f, 0.f, 0.f);
    for (int j = 0; j < C; j++) {
        float w = __expf(g_bm[mem[j] * HH + h] - gmax) * inv;
        float4 v = ((const float4*)(g_oacc + ((long)(mem[j] * HH + h)) * DVV))[t];
        acc.x += w * v.x; acc.y += w * v.y; acc.z += w * v.z; acc.w += w * v.w;
    }
    ((float4*)(out + ((long)(b * HH + h)) * DVV))[t] = acc;
}

// -----------------------------------------------------------------------------
// Inputs (metadata order): query f32 [32,16,576], key_cache f32 [1024,128,576],
// block_mapping f32 [512,32] (unused), block_bias f32 [512,128],
// block_list i32 [512], block_groups i32 [512]. Output f32 [32,16,512].
// -----------------------------------------------------------------------------
extern "C" void kernel_launch(void* const* d_in, const int* in_sizes, int n_in,
                              void* d_out, int out_size)
{
    const float* query        = (const float*)d_in[0];
    const float* key_cache    = (const float*)d_in[1];
    const float* block_bias   = (const float*)d_in[3];
    const int*   block_list   = (const int*)d_in[4];
    const int*   block_groups = (const int*)d_in[5];
    float* out = (float*)d_out;

    const int smem_bytes = SMEM_FLOATS * (int)sizeof(float);
    cudaFuncSetAttribute(mla_block_kernel,
                         cudaFuncAttributeMaxDynamicSharedMemorySize, smem_bytes);

    mla_block_kernel<<<NBLK, 256, smem_bytes>>>(
        query, key_cache, block_bias, block_list, block_groups);
    mla_combine_kernel<<<dim3(BQ, HH), 128>>>(block_groups, out);
}

// round 2
// speedup vs baseline: 2.4959x; 2.4959x over previous
#include <cuda_runtime.h>
#include <math.h>

// Problem constants (fixed by the dataset)
#define NBLK 512      // NB = B * BLOCKS_PER_SEQ
#define BQ   32       // B
#define HH   16       // H
#define DD   576      // KV_LORA + ROPE  (144 float4)
#define DD4  144
#define DVV  512      // KV_LORA
#define BSS  128      // BS (tokens per block)
#define QSCALE 0.07216878364870322f  // 192^-0.5

typedef unsigned long long ull;

// Scratch (device globals — no allocation allowed)
__device__ float g_oacc[NBLK * HH * DVV];   // 16 MB partial outputs
__device__ float g_bm[NBLK * HH];           // per-block max
__device__ float g_bs[NBLK * HH];           // per-block sum

__device__ __forceinline__ void fma2(ull& d, ull a, ull b) {
    asm("fma.rn.f32x2 %0, %1, %2, %0;" : "+l"(d) : "l"(a), "l"(b));
}
__device__ __forceinline__ float lo_f(ull v) { return __uint_as_float((unsigned)v); }
__device__ __forceinline__ float hi_f(ull v) { return __uint_as_float((unsigned)(v >> 32)); }
__device__ __forceinline__ ull dup2(float v) {
    unsigned u = __float_as_uint(v);
    return ((ull)u << 32) | u;
}

// -----------------------------------------------------------------------------
// SMEM layout (bytes):
//   qc  : 16 h x 17 float4   (one 64-d chunk of q, padded)     4352 B
//   kvs : 128 s x 17 float4  (K chunk, padded) / V tile 16x128  34816 B
//   attn: 16 h x 132 f32                                         8448 B
// total 47616 B -> 4 CTAs/SM
// -----------------------------------------------------------------------------
#define QC_STR4   17
#define KV_STR4   17
#define ATT_STRIDE 132
#define SMEM_BYTES (16*QC_STR4*16 + 128*KV_STR4*16 + HH*ATT_STRIDE*4)

__global__ __launch_bounds__(128, 4) void mla_block_kernel(
    const float* __restrict__ query,
    const float* __restrict__ key_cache,
    const float* __restrict__ block_bias,
    const int* __restrict__ block_list,
    const int* __restrict__ block_groups)
{
    extern __shared__ float sm[];
    float4* qc4   = (float4*)sm;                       // 16*17 float4
    float4* kvs4  = (float4*)(sm + 16 * QC_STR4 * 4);  // 128*17 float4
    float*  attn  = sm + (16 * QC_STR4 + 128 * KV_STR4) * 4;

    const int t = threadIdx.x;
    const int n = blockIdx.x;
    const int b = block_groups[n];
    const float4* kvb4 = (const float4*)(key_cache + (long)block_list[n] * (BSS * DD));
    const float4* q4   = (const float4*)query;

    // ================= Pass A: attn = scale * q . kv ========================
    // thread tile: 4 heads (h = hq + 4*i) x 4 s-rows (s = sq*4 + j)
    const int hq = t & 3;
    const int sq = t >> 2;

    ull acc2[4][4];
    #pragma unroll
    for (int i = 0; i < 4; i++)
        #pragma unroll
        for (int j = 0; j < 4; j++) acc2[i][j] = 0ull;

    for (int kc = 0; kc < 9; kc++) {
        __syncthreads();
        // stage q chunk: 256 float4 (pre-scaled)
        #pragma unroll
        for (int i = t; i < 256; i += 128) {
            int h = i >> 4, c = i & 15;
            float4 v = q4[(long)(b * HH + h) * DD4 + kc * 16 + c];
            v.x *= QSCALE; v.y *= QSCALE; v.z *= QSCALE; v.w *= QSCALE;
            qc4[h * QC_STR4 + c] = v;
        }
        // stage K chunk: 2048 float4
        #pragma unroll
        for (int i = t; i < 2048; i += 128) {
            int s = i >> 4, c = i & 15;
            kvs4[s * KV_STR4 + c] = kvb4[(long)s * DD4 + kc * 16 + c];
        }
        __syncthreads();

        #pragma unroll
        for (int k4 = 0; k4 < 16; k4++) {
            ull qp[4][2], kp[4][2];
            #pragma unroll
            for (int i = 0; i < 4; i++) {
                ulonglong2 qq = *(const ulonglong2*)&qc4[(hq + 4 * i) * QC_STR4 + k4];
                qp[i][0] = qq.x; qp[i][1] = qq.y;
            }
            #pragma unroll
            for (int j = 0; j < 4; j++) {
                ulonglong2 kk = *(const ulonglong2*)&kvs4[(sq * 4 + j) * KV_STR4 + k4];
                kp[j][0] = kk.x; kp[j][1] = kk.y;
            }
            #pragma unroll
            for (int i = 0; i < 4; i++)
                #pragma unroll
                for (int j = 0; j < 4; j++) {
                    fma2(acc2[i][j], qp[i][0], kp[j][0]);
                    fma2(acc2[i][j], qp[i][1], kp[j][1]);
                }
        }
    }
    __syncthreads();
    // merge lo+hi, add bias, write attn
    #pragma unroll
    for (int j = 0; j < 4; j++) {
        int s = sq * 4 + j;
        float bias = block_bias[n * BSS + s];
        #pragma unroll
        for (int i = 0; i < 4; i++) {
            int h = hq + 4 * i;
            attn[h * ATT_STRIDE + s] = lo_f(acc2[i][j]) + hi_f(acc2[i][j]) + bias;
        }
    }
    __syncthreads();

    // ================= Pass B: per-(n,h) softmax ===========================
    {
        int h = t >> 3, ln = t & 7;   // 8 lanes per head, 16 s each
        float m = -1e30f;
        #pragma unroll
        for (int r = 0; r < 16; r++)
            m = fmaxf(m, attn[h * ATT_STRIDE + ln + r * 8]);
        #pragma unroll
        for (int o = 4; o >= 1; o >>= 1)
            m = fmaxf(m, __shfl_xor_sync(0xffffffffu, m, o, 8));
        float l = 0.f;
        #pragma unroll
        for (int r = 0; r < 16; r++) {
            int idx = h * ATT_STRIDE + ln + r * 8;
            float p = __expf(attn[idx] - m);
            attn[idx] = p;
            l += p;
        }
        #pragma unroll
        for (int o = 4; o >= 1; o >>= 1)
            l += __shfl_xor_sync(0xffffffffu, l, o, 8);
        if (ln == 0) {
            g_bm[n * HH + h] = m;
            g_bs[n * HH + h] = l;
        }
    }

    // ================= Pass C: o = p @ v (f32x2 over v-pairs) ==============
    // thread tile: 4 heads (h = hb + 4*i) x 16 v (v = vb*16 .. +15)
    const int hb = t & 3;
    const int vb = t >> 2;   // 32 groups of 16 v

    ull o2[4][8];
    #pragma unroll
    for (int i = 0; i < 4; i++)
        #pragma unroll
        for (int p = 0; p < 8; p++) o2[i][p] = 0ull;

    for (int st = 0; st < 8; st++) {
        __syncthreads();
        // stage V tile: rows st*16..+16, first 512 floats (128 float4/row)
        #pragma unroll
        for (int i = t; i < 2048; i += 128) {
            int s = i >> 7, c = i & 127;
            kvs4[s * 128 + c] = kvb4[(long)(st * 16 + s) * DD4 + c];
        }
        __syncthreads();

        #pragma unroll
        for (int s = 0; s < 16; s++) {
            ull pd[4];
            #pragma unroll
            for (int i = 0; i < 4; i++)
                pd[i] = dup2(attn[(hb + 4 * i) * ATT_STRIDE + st * 16 + s]);
            #pragma unroll
            for (int c = 0; c < 4; c++) {
                ulonglong2 vv = *(const ulonglong2*)&kvs4[s * 128 + vb * 4 + c];
                #pragma unroll
                for (int i = 0; i < 4; i++) {
                    fma2(o2[i][2 * c],     pd[i], vv.x);
                    fma2(o2[i][2 * c + 1], pd[i], vv.y);
                }
            }
        }
    }

    // store partials (v-pairs are adjacent: direct 16B stores)
    #pragma unroll
    for (int i = 0; i < 4; i++) {
        int h = hb + 4 * i;
        ulonglong2* dst = (ulonglong2*)(g_oacc + ((long)(n * HH + h)) * DVV + vb * 16);
        #pragma unroll
        for (int c = 0; c < 4; c++) {
            ulonglong2 v; v.x = o2[i][2 * c]; v.y = o2[i][2 * c + 1];
            dst[c] = v;
        }
    }
}

// -----------------------------------------------------------------------------
// Combine: group b owns blocks n = b*16 .. b*16+15 (block_groups is
// repeat(arange(B), 16) in this dataset). Grid (B, H), 128 threads.
// -----------------------------------------------------------------------------
__global__ __launch_bounds__(128) void mla_combine_kernel(float* __restrict__ out)
{
    const int b = blockIdx.x, h = blockIdx.y, t = threadIdx.x;
    __shared__ float w[16];

    if (t < 16) {
        float m = g_bm[(b * 16 + t) * HH + h];
        float gmax = m;
        #pragma unroll
        for (int o = 8; o >= 1; o >>= 1)
            gmax = fmaxf(gmax, __shfl_xor_sync(0xffffu, gmax, o, 16));
        float e = __expf(m - gmax);
        float l = g_bs[(b * 16 + t) * HH + h] * e;
        float gsum = l;
        #pragma unroll
        for (int o = 8; o >= 1; o >>= 1)
            gsum += __shfl_xor_sync(0xffffu, gsum, o, 16);
        w[t] = e / gsum;
    }
    __syncthreads();

    float4 acc = make_float4(0.f, 0.f, 0.f, 0.f);
    #pragma unroll
    for (int j = 0; j < 16; j++) {
        float ww = w[j];
        float4 v = ((const float4*)(g_oacc + ((long)((b * 16 + j) * HH + h)) * DVV))[t];
        acc.x += ww * v.x; acc.y += ww * v.y; acc.z += ww * v.z; acc.w += ww * v.w;
    }
    ((float4*)(out + ((long)(b * HH + h)) * DVV))[t] = acc;
}

// -----------------------------------------------------------------------------
// Inputs (metadata order): query f32 [32,16,576], key_cache f32 [1024,128,576],
// block_mapping f32 [512,32] (unused), block_bias f32 [512,128],
// block_list i32 [512], block_groups i32 [512]. Output f32 [32,16,512].
// -----------------------------------------------------------------------------
extern "C" void kernel_launch(void* const* d_in, const int* in_sizes, int n_in,
                              void* d_out, int out_size)
{
    const float* query        = (const float*)d_in[0];
    const float* key_cache    = (const float*)d_in[1];
    const float* block_bias   = (const float*)d_in[3];
    const int*   block_list   = (const int*)d_in[4];
    const int*   block_groups = (const int*)d_in[5];
    float* out = (float*)d_out;

    cudaFuncSetAttribute(mla_block_kernel,
                         cudaFuncAttributeMaxDynamicSharedMemorySize, SMEM_BYTES);

    mla_block_kernel<<<NBLK, 128, SMEM_BYTES>>>(
        query, key_cache, block_bias, block_list, block_groups);
    mla_combine_kernel<<<dim3(BQ, HH), 128>>>(out);
}

// round 4
// speedup vs baseline: 2.9139x; 1.1675x over previous
#include <cuda_runtime.h>
#include <math.h>
#include <cstdint>

// Problem constants
#define NBLK 512
#define BQ   32
#define HH   16
#define DD   576
#define DD4  144
#define DVV  512
#define BSS  128
#define QSCALE 0.07216878364870322f  // 192^-0.5

typedef unsigned long long ull;

// Scratch (device globals — no allocation allowed)
__device__ float g_oacc[NBLK * HH * DVV];
__device__ float g_bm[NBLK * HH];
__device__ float g_bs[NBLK * HH];

// ---------------- helpers ----------------
__device__ __forceinline__ uint32_t smem_u32(const void* p) {
    uint32_t a;
    asm("{ .reg .u64 t; cvta.to.shared.u64 t, %1; cvt.u32.u64 %0, t; }" : "=r"(a) : "l"(p));
    return a;
}
__device__ __forceinline__ void cp16(uint32_t dst, const void* src) {
    asm volatile("cp.async.cg.shared.global [%0], [%1], 16;" :: "r"(dst), "l"(src));
}
#define CP_COMMIT() asm volatile("cp.async.commit_group;" ::: "memory")
#define CP_WAIT(n)  asm volatile("cp.async.wait_group %0;" :: "n"(n) : "memory")

__device__ __forceinline__ void fma2(ull& d, ull a, ull b) {
    asm("fma.rn.f32x2 %0, %1, %2, %0;" : "+l"(d) : "l"(a), "l"(b));
}
__device__ __forceinline__ float lo_f(ull v) { return __uint_as_float((unsigned)v); }
__device__ __forceinline__ float hi_f(ull v) { return __uint_as_float((unsigned)(v >> 32)); }
__device__ __forceinline__ ull dup2(float v) {
    unsigned u = __float_as_uint(v);
    return ((ull)u << 32) | u;
}

// ---------------- SMEM layout (bytes) ----------------
// [0, 36864)      : K chunk double buffer: buf b at b*18432, 128 rows x 9 float4
//                   (reused in Pass C as V double buffer: buf b at b*16384,
//                    8 rows x 128 float4)
// [36864, 41472)  : Q chunk double buffer: buf b at QOFF + b*2304, 16 x 9 float4
// [41472, 49920)  : attn f32 [16][132]
#define KBUFB 18432
#define KSTR  9
#define QOFF  36864
#define QBUFB 2304
#define ATTOFF 41472
#define ATT_STRIDE 132
#define SMEM_BYTES 49920

#define CHUNK_F4 8    // 32 d-floats per chunk
#define NCH 18        // 576 / 32

__global__ __launch_bounds__(128, 2) void mla_block_kernel(
    const float* __restrict__ query,
    const float* __restrict__ key_cache,
    const float* __restrict__ block_bias,
    const int* __restrict__ block_list,
    const int* __restrict__ block_groups)
{
    extern __shared__ char smem[];
    const uint32_t sbase = smem_u32(smem);
    const int t = threadIdx.x;
    const int n = blockIdx.x;
    const int b = block_groups[n];
    const float4* kvb4 = (const float4*)(key_cache + (long)block_list[n] * (BSS * DD));
    const float4* q4 = (const float4*)query;
    float* attn = (float*)(smem + ATTOFF);

    // loader thread mapping (Pass A)
    const int ls = t >> 3, lk = t & 7;   // q loader: h = ls, k = lk

    // ---- Pass A issue: chunk c -> buffer c&1 (K 1024 f4 + Q 128 f4)
    auto issueA = [&](int c) {
        uint32_t kb = sbase + (c & 1) * KBUFB;
        #pragma unroll
        for (int j = 0; j < 8; j++) {
            int i = t + j * 128;
            int s = i >> 3, k = i & 7;
            cp16(kb + (unsigned)(s * KSTR + k) * 16,
                 kvb4 + (long)s * DD4 + c * CHUNK_F4 + k);
        }
        cp16(sbase + QOFF + (c & 1) * QBUFB + (unsigned)(ls * KSTR + lk) * 16,
             q4 + (long)(b * HH + ls) * DD4 + c * CHUNK_F4 + lk);
        CP_COMMIT();
    };

    // ================= Pass A: attn = scale * q . kv =======================
    const int hq = t & 3;
    const int sq = t >> 2;

    ull acc2[4][4];
    #pragma unroll
    for (int i = 0; i < 4; i++)
        #pragma unroll
        for (int j = 0; j < 4; j++) acc2[i][j] = 0ull;

    issueA(0);
    issueA(1);

    for (int c = 0; c < NCH; c++) {
        if (c < NCH - 1) CP_WAIT(1); else CP_WAIT(0);
        __syncthreads();

        const float4* kvs4 = (const float4*)(smem + (c & 1) * KBUFB);
        const float4* qc4  = (const float4*)(smem + QOFF + (c & 1) * QBUFB);

        #pragma unroll
        for (int k4 = 0; k4 < 8; k4++) {
            ull qp[4][2], kp[4][2];
            #pragma unroll
            for (int i = 0; i < 4; i++) {
                ulonglong2 qq = *(const ulonglong2*)&qc4[(hq + 4 * i) * KSTR + k4];
                qp[i][0] = qq.x; qp[i][1] = qq.y;
            }
            #pragma unroll
            for (int j = 0; j < 4; j++) {
                ulonglong2 kk = *(const ulonglong2*)&kvs4[(sq * 4 + j) * KSTR + k4];
                kp[j][0] = kk.x; kp[j][1] = kk.y;
            }
            #pragma unroll
            for (int i = 0; i < 4; i++)
                #pragma unroll
                for (int j = 0; j < 4; j++) {
                    fma2(acc2[i][j], qp[i][0], kp[j][0]);
                    fma2(acc2[i][j], qp[i][1], kp[j][1]);
                }
        }
        __syncthreads();
        if (c + 2 < NCH) issueA(c + 2);
    }

    // merge lo+hi, apply scale, add bias, write attn
    #pragma unroll
    for (int j = 0; j < 4; j++) {
        int s = sq * 4 + j;
        float bias = block_bias[n * BSS + s];
        #pragma unroll
        for (int i = 0; i < 4; i++) {
            int h = hq + 4 * i;
            attn[h * ATT_STRIDE + s] =
                (lo_f(acc2[i][j]) + hi_f(acc2[i][j])) * QSCALE + bias;
        }
    }
    __syncthreads();

    // ---- Pass C prologue: start streaming V tiles 0,1 (overlaps softmax)
    auto issueC = [&](int tl) {
        uint32_t vbuf = sbase + (tl & 1) * 16384;
        #pragma unroll
        for (int j = 0; j < 8; j++) {
            int i = t + j * 128;
            int r = i >> 7, col = i & 127;
            cp16(vbuf + (unsigned)i * 16,
                 kvb4 + (long)(tl * 8 + r) * DD4 + col);
        }
        CP_COMMIT();
    };
    issueC(0);
    issueC(1);

    // ================= Pass B: per-(n,h) softmax ===========================
    {
        int h = t >> 3, ln = t & 7;
        float m = -1e30f;
        #pragma unroll
        for (int r = 0; r < 16; r++)
            m = fmaxf(m, attn[h * ATT_STRIDE + ln + r * 8]);
        #pragma unroll
        for (int o = 4; o >= 1; o >>= 1)
            m = fmaxf(m, __shfl_xor_sync(0xffffffffu, m, o, 8));
        float l = 0.f;
        #pragma unroll
        for (int r = 0; r < 16; r++) {
            int idx = h * ATT_STRIDE + ln + r * 8;
            float p = __expf(attn[idx] - m);
            attn[idx] = p;
            l += p;
        }
        #pragma unroll
        for (int o = 4; o >= 1; o >>= 1)
            l += __shfl_xor_sync(0xffffffffu, l, o, 8);
        if (ln == 0) {
            g_bm[n * HH + h] = m;
            g_bs[n * HH + h] = l;
        }
    }

    // ================= Pass C: o = p @ v (f32x2, 16 tiles of 8 rows) =======
    const int hb = t & 3;
    const int vb = t >> 2;

    ull o2[4][8];
    #pragma unroll
    for (int i = 0; i < 4; i++)
        #pragma unroll
        for (int p = 0; p < 8; p++) o2[i][p] = 0ull;

    for (int tl = 0; tl < 16; tl++) {
        if (tl < 15) CP_WAIT(1); else CP_WAIT(0);
        __syncthreads();

        const float4* vs4 = (const float4*)(smem + (tl & 1) * 16384);
        #pragma unroll
        for (int s = 0; s < 8; s++) {
            ull pd[4];
            #pragma unroll
            for (int i = 0; i < 4; i++)
                pd[i] = dup2(attn[(hb + 4 * i) * ATT_STRIDE + tl * 8 + s]);
            #pragma unroll
            for (int cc = 0; cc < 4; cc++) {
                ulonglong2 vv = *(const ulonglong2*)&vs4[s * 128 + vb * 4 + cc];
                #pragma unroll
                for (int i = 0; i < 4; i++) {
                    fma2(o2[i][2 * cc],     pd[i], vv.x);
                    fma2(o2[i][2 * cc + 1], pd[i], vv.y);
                }
            }
        }
        __syncthreads();
        if (tl + 2 < 16) issueC(tl + 2);
    }

    // store partials
    #pragma unroll
    for (int i = 0; i < 4; i++) {
        int h = hb + 4 * i;
        ulonglong2* dst = (ulonglong2*)(g_oacc + ((long)(n * HH + h)) * DVV + vb * 16);
        #pragma unroll
        for (int cc = 0; cc < 4; cc++) {
            ulonglong2 v; v.x = o2[i][2 * cc]; v.y = o2[i][2 * cc + 1];
            dst[cc] = v;
        }
    }
}

// ---------------- combine: group b owns blocks b*16..b*16+15 ----------------
// 512 threads: jq = t>>7 handles 4 of the 16 blocks; tree-reduce in smem.
__global__ __launch_bounds__(512) void mla_combine_kernel(float* __restrict__ out)
{
    const int b = blockIdx.x, h = blockIdx.y, t = threadIdx.x;
    __shared__ float w[16];
    __shared__ float4 red[2][128];

    if (t < 16) {
        float m = g_bm[(b * 16 + t) * HH + h];
        float gmax = m;
        #pragma unroll
        for (int o = 8; o >= 1; o >>= 1)
            gmax = fmaxf(gmax, __shfl_xor_sync(0xffffu, gmax, o, 16));
        float e = __expf(m - gmax);
        float gsum = g_bs[(b * 16 + t) * HH + h] * e;
        #pragma unroll
        for (int o = 8; o >= 1; o >>= 1)
            gsum += __shfl_xor_sync(0xffffu, gsum, o, 16);
        w[t] = e / gsum;
    }
    __syncthreads();

    const int jq = t >> 7;    // 0..3
    const int tt = t & 127;

    float4 acc = make_float4(0.f, 0.f, 0.f, 0.f);
    #pragma unroll
    for (int j = 0; j < 4; j++) {
        int blkj = jq * 4 + j;
        float ww = w[blkj];
        float4 v = ((const float4*)(g_oacc + ((long)((b * 16 + blkj) * HH + h)) * DVV))[tt];
        acc.x += ww * v.x; acc.y += ww * v.y; acc.z += ww * v.z; acc.w += ww * v.w;
    }
    if (jq >= 2) red[jq - 2][tt] = acc;
    __syncthreads();
    if (jq < 2) {
        float4 r = red[jq][tt];
        acc.x += r.x; acc.y += r.y; acc.z += r.z; acc.w += r.w;
    }
    __syncthreads();
    if (jq == 1) red[0][tt] = acc;
    __syncthreads();
    if (jq == 0) {
        float4 r = red[0][tt];
        acc.x += r.x; acc.y += r.y; acc.z += r.z; acc.w += r.w;
        ((float4*)(out + ((long)(b * HH + h)) * DVV))[tt] = acc;
    }
}

// -----------------------------------------------------------------------------
extern "C" void kernel_launch(void* const* d_in, const int* in_sizes, int n_in,
                              void* d_out, int out_size)
{
    const float* query        = (const float*)d_in[0];
    const float* key_cache    = (const float*)d_in[1];
    const float* block_bias   = (const float*)d_in[3];
    const int*   block_list   = (const int*)d_in[4];
    const int*   block_groups = (const int*)d_in[5];
    float* out = (float*)d_out;

    cudaFuncSetAttribute(mla_block_kernel,
                         cudaFuncAttributeMaxDynamicSharedMemorySize, SMEM_BYTES);

    mla_block_kernel<<<NBLK, 128, SMEM_BYTES>>>(
        query, key_cache, block_bias, block_list, block_groups);
    mla_combine_kernel<<<dim3(BQ, HH), 512>>>(out);
}

// round 5
// speedup vs baseline: 3.1656x; 1.0864x over previous
#include <cuda_runtime.h>
#include <math.h>
#include <cstdint>

// Problem constants
#define NBLK 512
#define BQ   32
#define HH   16
#define DD   576
#define DD4  144
#define DVV  512
#define BSS  128
#define QSCALE 0.07216878364870322f  // 192^-0.5

typedef unsigned long long ull;

// Scratch (device globals — no allocation allowed)
__device__ float g_oacc[NBLK * HH * DVV];
__device__ float g_bm[NBLK * HH];
__device__ float g_bs[NBLK * HH];

// ---------------- helpers ----------------
__device__ __forceinline__ uint32_t smem_u32(const void* p) {
    uint32_t a;
    asm("{ .reg .u64 t; cvta.to.shared.u64 t, %1; cvt.u32.u64 %0, t; }" : "=r"(a) : "l"(p));
    return a;
}
__device__ __forceinline__ void cp16(uint32_t dst, const void* src) {
    asm volatile("cp.async.cg.shared.global [%0], [%1], 16;" :: "r"(dst), "l"(src));
}
#define CP_COMMIT() asm volatile("cp.async.commit_group;" ::: "memory")
#define CP_WAIT(n)  asm volatile("cp.async.wait_group %0;" :: "n"(n) : "memory")

__device__ __forceinline__ void fma2(ull& d, ull a, ull b) {
    asm("fma.rn.f32x2 %0, %1, %2, %0;" : "+l"(d) : "l"(a), "l"(b));
}
__device__ __forceinline__ float lo_f(ull v) { return __uint_as_float((unsigned)v); }
__device__ __forceinline__ float hi_f(ull v) { return __uint_as_float((unsigned)(v >> 32)); }
__device__ __forceinline__ ull dup2(float v) {
    unsigned u = __float_as_uint(v);
    return ((ull)u << 32) | u;
}

// ---------------- SMEM layout (bytes) ----------------
// [0, 36864)      : K chunk double buffer: buf b at b*18432, 128 rows x 9 float4
//                   (reused in Pass C as V double buffer: buf b at b*16384,
//                    8 rows x 128 float4)
// [36864, 41472)  : Q chunk double buffer: buf b at QOFF + b*2304, 16 x 9 float4
// [41472, 49920)  : attn f32 [16][132]
#define KBUFB 18432
#define KSTR  9
#define QOFF  36864
#define QBUFB 2304
#define ATTOFF 41472
#define ATT_STRIDE 132
#define SMEM_BYTES 49920

#define CHUNK_F4 8    // 32 d-floats per chunk
#define NCH 18        // 576 / 32

__global__ __launch_bounds__(128, 3) void mla_block_kernel(
    const float* __restrict__ query,
    const float* __restrict__ key_cache,
    const float* __restrict__ block_bias,
    const int* __restrict__ block_list,
    const int* __restrict__ block_groups)
{
    extern __shared__ char smem[];
    const uint32_t sbase = smem_u32(smem);
    const int t = threadIdx.x;
    const int n = blockIdx.x;
    const int b = block_groups[n];
    const float4* kvb4 = (const float4*)(key_cache + (long)block_list[n] * (BSS * DD));
    const float4* q4 = (const float4*)query;
    float* attn = (float*)(smem + ATTOFF);

    // q loader mapping
    const int ls = t >> 3, lk = t & 7;

    // ---- Pass A issue: chunk c -> buffer c&1 (K 1024 f4 + Q 128 f4)
    auto issueA = [&](int c) {
        uint32_t kb = sbase + (c & 1) * KBUFB;
        #pragma unroll
        for (int j = 0; j < 8; j++) {
            int i = t + j * 128;
            int s = i >> 3, k = i & 7;
            cp16(kb + (unsigned)(s * KSTR + k) * 16,
                 kvb4 + (long)s * DD4 + c * CHUNK_F4 + k);
        }
        cp16(sbase + QOFF + (c & 1) * QBUFB + (unsigned)(ls * KSTR + lk) * 16,
             q4 + (long)(b * HH + ls) * DD4 + c * CHUNK_F4 + lk);
        CP_COMMIT();
    };

    // ================= Pass A: attn = scale * q . kv =======================
    // thread tile: h = hq + 4*i, s = sq + 32*j  (consecutive sq per warp ->
    // bank step 36 words mod 32 = 4 -> 8 distinct bank groups, conflict-free)
    const int hq = t & 3;
    const int sq = t >> 2;   // 0..31

    ull acc2[4][4];
    #pragma unroll
    for (int i = 0; i < 4; i++)
        #pragma unroll
        for (int j = 0; j < 4; j++) acc2[i][j] = 0ull;

    issueA(0);
    issueA(1);

    for (int c = 0; c < NCH; c++) {
        if (c < NCH - 1) CP_WAIT(1); else CP_WAIT(0);
        __syncthreads();

        const float4* kvs4 = (const float4*)(smem + (c & 1) * KBUFB);
        const float4* qc4  = (const float4*)(smem + QOFF + (c & 1) * QBUFB);

        #pragma unroll
        for (int k4 = 0; k4 < 8; k4++) {
            ull qp[4][2], kp[4][2];
            #pragma unroll
            for (int i = 0; i < 4; i++) {
                ulonglong2 qq = *(const ulonglong2*)&qc4[(hq + 4 * i) * KSTR + k4];
                qp[i][0] = qq.x; qp[i][1] = qq.y;
            }
            #pragma unroll
            for (int j = 0; j < 4; j++) {
                ulonglong2 kk = *(const ulonglong2*)&kvs4[(sq + 32 * j) * KSTR + k4];
                kp[j][0] = kk.x; kp[j][1] = kk.y;
            }
            #pragma unroll
            for (int i = 0; i < 4; i++)
                #pragma unroll
                for (int j = 0; j < 4; j++) {
                    fma2(acc2[i][j], qp[i][0], kp[j][0]);
                    fma2(acc2[i][j], qp[i][1], kp[j][1]);
                }
        }
        __syncthreads();
        if (c + 2 < NCH) issueA(c + 2);
    }

    // merge lo+hi, apply scale, add bias, write attn
    #pragma unroll
    for (int j = 0; j < 4; j++) {
        int s = sq + 32 * j;
        float bias = block_bias[n * BSS + s];
        #pragma unroll
        for (int i = 0; i < 4; i++) {
            int h = hq + 4 * i;
            attn[h * ATT_STRIDE + s] =
                (lo_f(acc2[i][j]) + hi_f(acc2[i][j])) * QSCALE + bias;
        }
    }
    __syncthreads();

    // ---- Pass C prologue: start streaming V tiles 0,1 (overlaps softmax)
    auto issueC = [&](int tl) {
        uint32_t vbuf = sbase + (tl & 1) * 16384;
        #pragma unroll
        for (int j = 0; j < 8; j++) {
            int i = t + j * 128;
            int r = i >> 7, col = i & 127;
            cp16(vbuf + (unsigned)i * 16,
                 kvb4 + (long)(tl * 8 + r) * DD4 + col);
        }
        CP_COMMIT();
    };
    issueC(0);
    issueC(1);

    // ================= Pass B: per-(n,h) softmax ===========================
    {
        int h = t >> 3, ln = t & 7;
        float m = -1e30f;
        #pragma unroll
        for (int r = 0; r < 16; r++)
            m = fmaxf(m, attn[h * ATT_STRIDE + ln + r * 8]);
        #pragma unroll
        for (int o = 4; o >= 1; o >>= 1)
            m = fmaxf(m, __shfl_xor_sync(0xffffffffu, m, o, 8));
        float l = 0.f;
        #pragma unroll
        for (int r = 0; r < 16; r++) {
            int idx = h * ATT_STRIDE + ln + r * 8;
            float p = __expf(attn[idx] - m);
            attn[idx] = p;
            l += p;
        }
        #pragma unroll
        for (int o = 4; o >= 1; o >>= 1)
            l += __shfl_xor_sync(0xffffffffu, l, o, 8);
        if (ln == 0) {
            g_bm[n * HH + h] = m;
            g_bs[n * HH + h] = l;
        }
    }

    // ================= Pass C: o = p @ v (f32x2, 16 tiles of 8 rows) =======
    // thread tile: h = hb + 4*i, v-float4 columns {vb, vb+32, vb+64, vb+96}
    // (consecutive vb per warp -> contiguous 128B lines, conflict-free)
    const int hb = t & 3;
    const int vb = t >> 2;   // 0..31

    ull o2[4][8];
    #pragma unroll
    for (int i = 0; i < 4; i++)
        #pragma unroll
        for (int p = 0; p < 8; p++) o2[i][p] = 0ull;

    for (int tl = 0; tl < 16; tl++) {
        if (tl < 15) CP_WAIT(1); else CP_WAIT(0);
        __syncthreads();

        const float4* vs4 = (const float4*)(smem + (tl & 1) * 16384);
        #pragma unroll
        for (int s = 0; s < 8; s++) {
            ull pd[4];
            #pragma unroll
            for (int i = 0; i < 4; i++)
                pd[i] = dup2(attn[(hb + 4 * i) * ATT_STRIDE + tl * 8 + s]);
            #pragma unroll
            for (int cc = 0; cc < 4; cc++) {
                ulonglong2 vv = *(const ulonglong2*)&vs4[s * 128 + vb + cc * 32];
                #pragma unroll
                for (int i = 0; i < 4; i++) {
                    fma2(o2[i][2 * cc],     pd[i], vv.x);
                    fma2(o2[i][2 * cc + 1], pd[i], vv.y);
                }
            }
        }
        __syncthreads();
        if (tl + 2 < 16) issueC(tl + 2);
    }

    // store partials (each thread: 4 float4s per h at column vb + cc*32)
    #pragma unroll
    for (int i = 0; i < 4; i++) {
        int h = hb + 4 * i;
        ulonglong2* dst = (ulonglong2*)(g_oacc + ((long)(n * HH + h)) * DVV);
        #pragma unroll
        for (int cc = 0; cc < 4; cc++) {
            ulonglong2 v; v.x = o2[i][2 * cc]; v.y = o2[i][2 * cc + 1];
            dst[vb + cc * 32] = v;
        }
    }
}

// ---------------- combine: group b owns blocks b*16..b*16+15 ----------------
// 256 threads, each owns a float2; all 16 block loads in flight (MLP=16).
__global__ __launch_bounds__(256) void mla_combine_kernel(float* __restrict__ out)
{
    const int b = blockIdx.x, h = blockIdx.y, t = threadIdx.x;
    __shared__ float w[16];

    if (t < 16) {
        float m = g_bm[(b * 16 + t) * HH + h];
        float gmax = m;
        #pragma unroll
        for (int o = 8; o >= 1; o >>= 1)
            gmax = fmaxf(gmax, __shfl_xor_sync(0xffffu, gmax, o, 16));
        float e = __expf(m - gmax);
        float gsum = g_bs[(b * 16 + t) * HH + h] * e;
        #pragma unroll
        for (int o = 8; o >= 1; o >>= 1)
            gsum += __shfl_xor_sync(0xffffu, gsum, o, 16);
        w[t] = e / gsum;
    }
    __syncthreads();

    float2 v[16];
    #pragma unroll
    for (int j = 0; j < 16; j++)
        v[j] = ((const float2*)(g_oacc + ((long)((b * 16 + j) * HH + h)) * DVV))[t];

    float2 acc = make_float2(0.f, 0.f);
    #pragma unroll
    for (int j = 0; j < 16; j++) {
        float ww = w[j];
        acc.x += ww * v[j].x;
        acc.y += ww * v[j].y;
    }
    ((float2*)(out + ((long)(b * HH + h)) * DVV))[t] = acc;
}

// -----------------------------------------------------------------------------
extern "C" void kernel_launch(void* const* d_in, const int* in_sizes, int n_in,
                              void* d_out, int out_size)
{
    const float* query        = (const float*)d_in[0];
    const float* key_cache    = (const float*)d_in[1];
    const float* block_bias   = (const float*)d_in[3];
    const int*   block_list   = (const int*)d_in[4];
    const int*   block_groups = (const int*)d_in[5];
    float* out = (float*)d_out;

    cudaFuncSetAttribute(mla_block_kernel,
                         cudaFuncAttributeMaxDynamicSharedMemorySize, SMEM_BYTES);

    mla_block_kernel<<<NBLK, 128, SMEM_BYTES>>>(
        query, key_cache, block_bias, block_list, block_groups);
    mla_combine_kernel<<<dim3(BQ, HH), 256>>>(out);
}